// round 8
// baseline (speedup 1.0000x reference)
#include <cuda_runtime.h>
#include <cstdint>

// DotProductAttention (B=4, C=80, 512x512 fp32). Pure HBM stream, 369MB.
// R8 = R6 producer (80 x 1KB cp.async.bulk per tile, warp-distributed,
// L2 evict-first) + early-refill consumer: pull ALL smem reads (q, k, v)
// into registers, sync, issue the stage refill, THEN run softmax + stores
// while the next loads are in flight. Removes ~500-700 cyc/tile of TMA
// starvation behind the epilogue.

#define NK_   8
#define NV_   8
#define NCH_  80
#define HW_   262144                 // 512*512
#define PIX_  256                    // pixels per tile
#define CHUNKS_PER_B (HW_ / PIX_)    // 1024
#define TOTAL_CHUNKS (CHUNKS_PER_B * 4)     // 4096
#define TILE_BYTES (NCH_ * PIX_ * 4)        // 81920
#define SMEM_BARS 128
#define SMEM_TOTAL (SMEM_BARS + 2 * TILE_BYTES)   // 163968
#define GRID_    148
#define THREADS_ 256
#define CH_PER_WARP 10               // 80 channels / 8 warps

__device__ __forceinline__ uint32_t smem_u32(const void* p) {
    return (uint32_t)__cvta_generic_to_shared(p);
}
__device__ __forceinline__ void mbar_init(uint32_t a, uint32_t cnt) {
    asm volatile("mbarrier.init.shared.b64 [%0], %1;" :: "r"(a), "r"(cnt) : "memory");
}
__device__ __forceinline__ void mbar_expect_tx(uint32_t a, uint32_t bytes) {
    asm volatile("mbarrier.arrive.expect_tx.shared.b64 _, [%0], %1;"
                 :: "r"(a), "r"(bytes) : "memory");
}
__device__ __forceinline__ void mbar_wait(uint32_t a, uint32_t parity) {
    asm volatile(
        "{\n\t.reg .pred P;\n\t"
        "WAIT_%=:\n\t"
        "mbarrier.try_wait.parity.acquire.cta.shared::cta.b64 P, [%0], %1, 0x989680;\n\t"
        "@P bra.uni DONE_%=;\n\t"
        "bra.uni WAIT_%=;\n\t"
        "DONE_%=:\n\t}"
        :: "r"(a), "r"(parity) : "memory");
}
__device__ __forceinline__ void bulk_g2s(uint32_t dst, const void* src,
                                         uint32_t bytes, uint32_t mbar,
                                         uint64_t pol) {
    asm volatile(
        "cp.async.bulk.shared::cluster.global.mbarrier::complete_tx::bytes"
        ".L2::cache_hint [%0], [%1], %2, [%3], %4;"
        :: "r"(dst), "l"(src), "r"(bytes), "r"(mbar), "l"(pol) : "memory");
}

// exp2 of t (t <= 0, clamped >= -80), FMA/ALU only. Rel err ~2e-6.
__device__ __forceinline__ float fast_exp2(float t) {
    t = fmaxf(t, -80.0f);
    float tf = t + 12582912.0f;                 // 1.5 * 2^23 : round-to-nearest
    int   n  = __float_as_int(tf);
    float f  = t - (tf - 12582912.0f);          // f in [-0.5, 0.5]
    float p = 1.33335581e-3f;
    p = fmaf(p, f, 9.61812911e-3f);
    p = fmaf(p, f, 5.55041087e-2f);
    p = fmaf(p, f, 2.40226507e-1f);
    p = fmaf(p, f, 6.93147182e-1f);
    p = fmaf(p, f, 1.0f);
    return __int_as_float(__float_as_int(p) + (n << 23));
}

__global__ void __launch_bounds__(THREADS_, 1)
dpa_kernel(const float* __restrict__ inp, float* __restrict__ out)
{
    extern __shared__ char smem[];
    const uint32_t sbase = smem_u32(smem);
    const int tid = threadIdx.x;
    const int warp = tid >> 5;
    const bool lane0 = (tid & 31) == 0;

    const uint32_t full0 = sbase;               // two mbarriers: +0, +8
    const uint32_t tile_s0 = sbase + SMEM_BARS;

    uint64_t pol;
    asm("createpolicy.fractional.L2::evict_first.b64 %0, 1.0;" : "=l"(pol));

    if (tid == 0) {
        mbar_init(full0, 8);                    // 8 producer-warp arrivals
        mbar_init(full0 + 8, 8);
        asm volatile("fence.proxy.async.shared::cta;" ::: "memory");
    }
    __syncthreads();

    // warp-distributed issue: this warp's 10 channel slices into stage s
    auto issue_tile = [&](int s, int chunk) {
        const int b  = chunk >> 10;             // / CHUNKS_PER_B
        const int cb = chunk & (CHUNKS_PER_B - 1);
        const float* src0 = inp + (size_t)b * NCH_ * HW_ + cb * PIX_;
        const uint32_t dst0 = tile_s0 + s * TILE_BYTES;
        const uint32_t mb = full0 + s * 8;
        mbar_expect_tx(mb, CH_PER_WARP * PIX_ * 4);
        const int c0 = warp * CH_PER_WARP;
#pragma unroll
        for (int c = 0; c < CH_PER_WARP; c++)
            bulk_g2s(dst0 + (c0 + c) * (PIX_ * 4),
                     src0 + (size_t)(c0 + c) * HW_, PIX_ * 4, mb, pol);
    };

    // prologue: fill both stages
    if (lane0) {
        if (blockIdx.x < TOTAL_CHUNKS)          issue_tile(0, blockIdx.x);
        if (blockIdx.x + GRID_ < TOTAL_CHUNKS)  issue_tile(1, blockIdx.x + GRID_);
    }

    const float C = 0.51006952f;                // log2(e)/sqrt(8)

    for (int j = 0, chunk = blockIdx.x; chunk < TOTAL_CHUNKS;
         j++, chunk += GRID_) {
        const int s = j & 1;
        const uint32_t parity = (j >> 1) & 1;
        mbar_wait(full0 + s * 8, parity);

        const float* tile = (const float*)(smem + SMEM_BARS + s * TILE_BYTES);

        // ---- phase 1: ALL smem reads -> registers ----
        float q[NK_];
#pragma unroll
        for (int i = 0; i < NK_; i++)
            q[i] = tile[i * PIX_ + tid];

        float qk[NV_];
#pragma unroll
        for (int v = 0; v < NV_; v++) qk[v] = 0.0f;
#pragma unroll
        for (int kk = 0; kk < NK_; kk++) {
#pragma unroll
            for (int v = 0; v < NV_; v++)
                qk[v] = fmaf(q[kk], tile[(NK_ + kk * NV_ + v) * PIX_ + tid], qk[v]);
        }

        float vv[NV_];
#pragma unroll
        for (int v = 0; v < NV_; v++)
            vv[v] = tile[(NK_ + NK_ * NV_ + v) * PIX_ + tid];

        // ---- stage s no longer read by anyone: refill NOW ----
        __syncthreads();
        {
            const int cn = chunk + 2 * GRID_;
            if (lane0 && cn < TOTAL_CHUNKS)
                issue_tile(s, cn);
        }

        // ---- phase 2: softmax + stores, overlapped with in-flight loads ----
        float m = qk[0];
#pragma unroll
        for (int v = 1; v < NV_; v++) m = fmaxf(m, qk[v]);
        const float mC = m * C;
        float ssum = 0.0f;
#pragma unroll
        for (int v = 0; v < NV_; v++) {
            qk[v] = fast_exp2(fmaf(qk[v], C, -mC));   // 2^(C*(qk-m))
            ssum += qk[v];
        }
        const float inv = __frcp_rn(ssum);

        const int b  = chunk >> 10;
        const int cb = chunk & (CHUNKS_PER_B - 1);
        float* obase = out + (size_t)b * NV_ * HW_ + cb * PIX_ + tid;
#pragma unroll
        for (int v = 0; v < NV_; v++)
            __stcs(obase + v * HW_, qk[v] * inv * vv[v]);
    }
}

extern "C" void kernel_launch(void* const* d_in, const int* in_sizes, int n_in,
                              void* d_out, int out_size)
{
    const float* inp = (const float*)d_in[0];
    float* out = (float*)d_out;
    static int configured = 0;
    if (!configured) {
        cudaFuncSetAttribute(dpa_kernel,
                             cudaFuncAttributeMaxDynamicSharedMemorySize,
                             SMEM_TOTAL);
        configured = 1;
    }
    dpa_kernel<<<GRID_, THREADS_, SMEM_TOTAL>>>(inp, out);
}

// round 9
// speedup vs baseline: 1.0622x; 1.0622x over previous
#include <cuda_runtime.h>
#include <cstdint>

// DotProductAttention (B=4, C=80, 512x512 fp32). Pure HBM stream, 369MB.
// R9 = R6 producer (80 x 1KB cp.async.bulk in, warp-distributed, L2
// evict-first) + early refill + TMA bulk STORES: outputs staged in 2 x 8KB
// smem buffers and written as 8 x 1KB cp.async.bulk smem->global bursts
// (full-line writes, no per-thread STG in the epilogue).

#define NK_   8
#define NV_   8
#define NCH_  80
#define HW_   262144                 // 512*512
#define PIX_  256                    // pixels per tile
#define CHUNKS_PER_B (HW_ / PIX_)    // 1024
#define TOTAL_CHUNKS (CHUNKS_PER_B * 4)     // 4096
#define TILE_BYTES (NCH_ * PIX_ * 4)        // 81920
#define OUT_BYTES  (NV_ * PIX_ * 4)         // 8192
#define SMEM_BARS 128
#define SMEM_TOTAL (SMEM_BARS + 2 * TILE_BYTES + 2 * OUT_BYTES)  // 180352
#define GRID_    148
#define THREADS_ 256
#define CH_PER_WARP 10               // 80 channels / 8 warps

__device__ __forceinline__ uint32_t smem_u32(const void* p) {
    return (uint32_t)__cvta_generic_to_shared(p);
}
__device__ __forceinline__ void mbar_init(uint32_t a, uint32_t cnt) {
    asm volatile("mbarrier.init.shared.b64 [%0], %1;" :: "r"(a), "r"(cnt) : "memory");
}
__device__ __forceinline__ void mbar_expect_tx(uint32_t a, uint32_t bytes) {
    asm volatile("mbarrier.arrive.expect_tx.shared.b64 _, [%0], %1;"
                 :: "r"(a), "r"(bytes) : "memory");
}
__device__ __forceinline__ void mbar_wait(uint32_t a, uint32_t parity) {
    asm volatile(
        "{\n\t.reg .pred P;\n\t"
        "WAIT_%=:\n\t"
        "mbarrier.try_wait.parity.acquire.cta.shared::cta.b64 P, [%0], %1, 0x989680;\n\t"
        "@P bra.uni DONE_%=;\n\t"
        "bra.uni WAIT_%=;\n\t"
        "DONE_%=:\n\t}"
        :: "r"(a), "r"(parity) : "memory");
}
__device__ __forceinline__ void bulk_g2s(uint32_t dst, const void* src,
                                         uint32_t bytes, uint32_t mbar,
                                         uint64_t pol) {
    asm volatile(
        "cp.async.bulk.shared::cluster.global.mbarrier::complete_tx::bytes"
        ".L2::cache_hint [%0], [%1], %2, [%3], %4;"
        :: "r"(dst), "l"(src), "r"(bytes), "r"(mbar), "l"(pol) : "memory");
}
__device__ __forceinline__ void bulk_s2g(void* dst, uint32_t src,
                                         uint32_t bytes, uint64_t pol) {
    asm volatile(
        "cp.async.bulk.global.shared::cta.bulk_group.L2::cache_hint "
        "[%0], [%1], %2, %3;"
        :: "l"(dst), "r"(src), "r"(bytes), "l"(pol) : "memory");
}
__device__ __forceinline__ void bulk_commit() {
    asm volatile("cp.async.bulk.commit_group;" ::: "memory");
}
template <int N>
__device__ __forceinline__ void bulk_wait() {
    asm volatile("cp.async.bulk.wait_group %0;" :: "n"(N) : "memory");
}

// exp2 of t (t <= 0, clamped >= -80), FMA/ALU only. Rel err ~2e-6.
__device__ __forceinline__ float fast_exp2(float t) {
    t = fmaxf(t, -80.0f);
    float tf = t + 12582912.0f;                 // 1.5 * 2^23 : round-to-nearest
    int   n  = __float_as_int(tf);
    float f  = t - (tf - 12582912.0f);          // f in [-0.5, 0.5]
    float p = 1.33335581e-3f;
    p = fmaf(p, f, 9.61812911e-3f);
    p = fmaf(p, f, 5.55041087e-2f);
    p = fmaf(p, f, 2.40226507e-1f);
    p = fmaf(p, f, 6.93147182e-1f);
    p = fmaf(p, f, 1.0f);
    return __int_as_float(__float_as_int(p) + (n << 23));
}

__global__ void __launch_bounds__(THREADS_, 1)
dpa_kernel(const float* __restrict__ inp, float* __restrict__ out)
{
    extern __shared__ char smem[];
    const uint32_t sbase = smem_u32(smem);
    const int tid = threadIdx.x;
    const int warp = tid >> 5;
    const bool lane0 = (tid & 31) == 0;

    const uint32_t full0 = sbase;               // two mbarriers: +0, +8
    const uint32_t tile_s0 = sbase + SMEM_BARS;
    const uint32_t ostage0 = sbase + SMEM_BARS + 2 * TILE_BYTES;
    float* const ostage_f = (float*)(smem + SMEM_BARS + 2 * TILE_BYTES);

    uint64_t pol;
    asm("createpolicy.fractional.L2::evict_first.b64 %0, 1.0;" : "=l"(pol));

    if (tid == 0) {
        mbar_init(full0, 8);                    // 8 producer-warp arrivals
        mbar_init(full0 + 8, 8);
        asm volatile("fence.proxy.async.shared::cta;" ::: "memory");
    }
    __syncthreads();

    // warp-distributed issue: this warp's 10 channel slices into stage s
    auto issue_tile = [&](int s, int chunk) {
        const int b  = chunk >> 10;             // / CHUNKS_PER_B
        const int cb = chunk & (CHUNKS_PER_B - 1);
        const float* src0 = inp + (size_t)b * NCH_ * HW_ + cb * PIX_;
        const uint32_t dst0 = tile_s0 + s * TILE_BYTES;
        const uint32_t mb = full0 + s * 8;
        mbar_expect_tx(mb, CH_PER_WARP * PIX_ * 4);
        const int c0 = warp * CH_PER_WARP;
#pragma unroll
        for (int c = 0; c < CH_PER_WARP; c++)
            bulk_g2s(dst0 + (c0 + c) * (PIX_ * 4),
                     src0 + (size_t)(c0 + c) * HW_, PIX_ * 4, mb, pol);
    };

    // prologue: fill both input stages
    if (lane0) {
        if (blockIdx.x < TOTAL_CHUNKS)          issue_tile(0, blockIdx.x);
        if (blockIdx.x + GRID_ < TOTAL_CHUNKS)  issue_tile(1, blockIdx.x + GRID_);
    }

    const float C = 0.51006952f;                // log2(e)/sqrt(8)

    for (int j = 0, chunk = blockIdx.x; chunk < TOTAL_CHUNKS;
         j++, chunk += GRID_) {
        const int s = j & 1;
        const uint32_t parity = (j >> 1) & 1;
        mbar_wait(full0 + s * 8, parity);

        const float* tile = (const float*)(smem + SMEM_BARS + s * TILE_BYTES);

        // ---- phase 1: all input-stage reads -> registers ----
        float q[NK_];
#pragma unroll
        for (int i = 0; i < NK_; i++)
            q[i] = tile[i * PIX_ + tid];

        float qk[NV_];
#pragma unroll
        for (int v = 0; v < NV_; v++) qk[v] = 0.0f;
#pragma unroll
        for (int kk = 0; kk < NK_; kk++) {
#pragma unroll
            for (int v = 0; v < NV_; v++)
                qk[v] = fmaf(q[kk], tile[(NK_ + kk * NV_ + v) * PIX_ + tid], qk[v]);
        }

        float vv[NV_];
#pragma unroll
        for (int v = 0; v < NV_; v++)
            vv[v] = tile[(NK_ + NK_ * NV_ + v) * PIX_ + tid];

        // ---- input stage s free: refill immediately ----
        __syncthreads();
        {
            const int cn = chunk + 2 * GRID_;
            if (lane0 && cn < TOTAL_CHUNKS)
                issue_tile(s, cn);
        }

        // ---- softmax (overlapped with in-flight loads) ----
        float m = qk[0];
#pragma unroll
        for (int v = 1; v < NV_; v++) m = fmaxf(m, qk[v]);
        const float mC = m * C;
        float ssum = 0.0f;
#pragma unroll
        for (int v = 0; v < NV_; v++) {
            qk[v] = fast_exp2(fmaf(qk[v], C, -mC));   // 2^(C*(qk-m))
            ssum += qk[v];
        }
        const float inv = __frcp_rn(ssum);

        // ---- output staging: ensure out-stage s (iter j-2) drained ----
        if (tid < NV_) bulk_wait<1>();
        __syncthreads();

        float* ost = ostage_f + s * (NV_ * PIX_);
#pragma unroll
        for (int v = 0; v < NV_; v++)
            ost[v * PIX_ + tid] = qk[v] * inv * vv[v];

        __syncthreads();
        if (tid < NV_) {
            asm volatile("fence.proxy.async.shared::cta;" ::: "memory");
            const int b  = chunk >> 10;
            const int cb = chunk & (CHUNKS_PER_B - 1);
            float* dst = out + (size_t)b * NV_ * HW_ + (size_t)tid * HW_ + cb * PIX_;
            bulk_s2g(dst, ostage0 + s * OUT_BYTES + tid * (PIX_ * 4),
                     PIX_ * 4, pol);
            bulk_commit();
        }
    }

    if (tid < NV_) bulk_wait<0>();
}

extern "C" void kernel_launch(void* const* d_in, const int* in_sizes, int n_in,
                              void* d_out, int out_size)
{
    const float* inp = (const float*)d_in[0];
    float* out = (float*)d_out;
    static int configured = 0;
    if (!configured) {
        cudaFuncSetAttribute(dpa_kernel,
                             cudaFuncAttributeMaxDynamicSharedMemorySize,
                             SMEM_TOTAL);
        configured = 1;
    }
    dpa_kernel<<<GRID_, THREADS_, SMEM_TOTAL>>>(inp, out);
}